// round 6
// baseline (speedup 1.0000x reference)
#include <cuda_runtime.h>
#include <math.h>

#define NCHUNKS 2048
#define CHUNK4  2048               // float4 per chunk (per array) = 32KB/array
#define NC      4                  // ticket counters
#define BLOCKS  296                // 2 CTAs per SM
#define THREADS 512
#define NWARPS  16
#define WSLICE  (CHUNK4 / NWARPS)  // 128 float4 per warp per chunk
                                   // -> 4 float4 pairs per thread

// Per-(chunk,warp) partials, keyed by CHUNK (not block) -> bitwise
// deterministic output regardless of dynamic chunk->CTA mapping.
__device__ float2 g_partials[NCHUNKS * NWARPS];
__device__ unsigned int g_tickets[NC * 32];   // 128B-padded counters, static 0
__device__ unsigned int g_done;               // static 0, reset each call

// exp via ex2.approx; coefficients pre-scaled by log2(e):
//   d>=0: exp(d/10) = 2^(d*log2e/10);  d<0: exp(-d/13) = 2^(-d*log2e/13)
// fmax(d*c1, d*c2) picks the right one for both signs.
#define C_POS ( 0.14426950408889634f)
#define C_NEG (-0.11097654160684334f)

__device__ __forceinline__ float ex2_approx(float x) {
    float r;
    asm("ex2.approx.f32 %0, %1;" : "=f"(r) : "f"(x));
    return r;
}

__device__ __forceinline__ void accum_elem(float p, float t, float& s_exp, float& s_sq) {
    float d = p - t;
    s_sq = fmaf(d, d, s_sq);
    float arg = fmaxf(d * C_POS, d * C_NEG);
    s_exp += ex2_approx(arg);      // the -1 is applied once at the end
}

__device__ __forceinline__ void accum4(float4 a, float4 b, float& s_exp, float& s_sq) {
    accum_elem(a.x, b.x, s_exp, s_sq);
    accum_elem(a.y, b.y, s_exp, s_sq);
    accum_elem(a.z, b.z, s_exp, s_sq);
    accum_elem(a.w, b.w, s_exp, s_sq);
}

__global__ void __launch_bounds__(THREADS, 2) fused_loss_kernel(
    const float4* __restrict__ pred, const float4* __restrict__ tru,
    const float* __restrict__ theta_ptr, float* __restrict__ out,
    int tpc,              // tickets per counter = NCHUNKS / NC
    float inv_n)
{
    __shared__ int sh_t[2];
    __shared__ double sh_a[NWARPS];
    __shared__ double sh_b[NWARPS];
    __shared__ bool sh_last;

    const int tid = threadIdx.x;
    const int wid = tid >> 5;
    const int lid = tid & 31;
    const int cid = blockIdx.x & (NC - 1);
    unsigned int* ticket = &g_tickets[cid * 32];

    if (tid == 0) sh_t[0] = (int)atomicAdd(ticket, 1u);
    __syncthreads();

    int buf = 0;
    for (;;) {
        int t = sh_t[buf];
        if (t >= tpc) break;
        // Prefetch next ticket while this chunk streams (latency hidden)
        if (tid == 0) sh_t[buf ^ 1] = (int)atomicAdd(ticket, 1u);

        int chunk = t * NC + cid;
        int base = chunk * CHUNK4 + wid * WSLICE + lid;

        // Front-batch 8 independent LDG.128
        float4 a0 = pred[base];      float4 b0 = tru[base];
        float4 a1 = pred[base + 32]; float4 b1 = tru[base + 32];
        float4 a2 = pred[base + 64]; float4 b2 = tru[base + 64];
        float4 a3 = pred[base + 96]; float4 b3 = tru[base + 96];

        float s_exp = 0.0f, s_sq = 0.0f;
        accum4(a0, b0, s_exp, s_sq);
        accum4(a1, b1, s_exp, s_sq);
        accum4(a2, b2, s_exp, s_sq);
        accum4(a3, b3, s_exp, s_sq);

        // Fixed-order warp reduce -> per-(chunk,warp) partial
        #pragma unroll
        for (int off = 16; off > 0; off >>= 1) {
            s_exp += __shfl_down_sync(0xFFFFFFFFu, s_exp, off);
            s_sq  += __shfl_down_sync(0xFFFFFFFFu, s_sq, off);
        }
        if (lid == 0)
            g_partials[chunk * NWARPS + wid] = make_float2(s_exp, s_sq);

        __syncthreads();   // publish prefetched ticket to all threads
        buf ^= 1;
    }

    // Publish partial stores, then signal completion
    __threadfence();
    __syncthreads();
    if (tid == 0) {
        unsigned int prev = atomicAdd(&g_done, 1u);
        sh_last = (prev == (unsigned int)(gridDim.x - 1));
    }
    __syncthreads();

    if (sh_last) {
        __threadfence();   // acquire: see all partials
        // Deterministic final reduce: fixed index order, coalesced
        double f_exp = 0.0, f_sq = 0.0;
        #pragma unroll 4
        for (int k = 0; k < (NCHUNKS * NWARPS) / THREADS; k++) {
            float2 v = g_partials[k * THREADS + tid];
            f_exp += (double)v.x;
            f_sq  += (double)v.y;
        }
        #pragma unroll
        for (int off = 16; off > 0; off >>= 1) {
            f_exp += __shfl_down_sync(0xFFFFFFFFu, f_exp, off);
            f_sq  += __shfl_down_sync(0xFFFFFFFFu, f_sq, off);
        }
        if (lid == 0) { sh_a[wid] = f_exp; sh_b[wid] = f_sq; }
        __syncthreads();
        if (tid == 0) {
            double esum = 0.0, sq = 0.0;
            #pragma unroll
            for (int w = 0; w < NWARPS; w++) { esum += sh_a[w]; sq += sh_b[w]; }
            double n_total = (double)NCHUNKS * (double)CHUNK4 * 4.0;
            double score = esum - n_total;          // sum(exp(...) - 1)
            float theta = theta_ptr[0];
            double rmse = sqrt(sq * (double)inv_n);
            out[0] = (float)((double)theta * score + (1.0 - (double)theta) * rmse);
            // Reset scheduler state for next graph replay
            g_done = 0u;
            #pragma unroll
            for (int c = 0; c < NC; c++) g_tickets[c * 32] = 0u;
        }
    }
}

extern "C" void kernel_launch(void* const* d_in, const int* in_sizes, int n_in,
                              void* d_out, int out_size) {
    const float* pred  = (const float*)d_in[0];
    const float* tru   = (const float*)d_in[1];
    const float* theta = (const float*)d_in[2];
    float* out = (float*)d_out;

    int n = in_sizes[0];               // 16777216 = NCHUNKS*CHUNK4*4
    int tpc = NCHUNKS / NC;            // 512

    fused_loss_kernel<<<BLOCKS, THREADS>>>(
        (const float4*)pred, (const float4*)tru, theta, out,
        tpc, 1.0f / (float)n);
}

// round 7
// speedup vs baseline: 2.0950x; 2.0950x over previous
#include <cuda_runtime.h>
#include <math.h>

#define REDUCE_BLOCKS (148 * 8)   // 1184
#define REDUCE_THREADS 256
#define FIN_THREADS 1024

// Per-block partials: each block overwrites its own slot -> no zeroing needed.
__device__ double2 g_partials[REDUCE_BLOCKS];

// exp via ex2.approx; coefficients pre-scaled by log2(e):
//   d>=0: exp(d/10) = 2^(d*log2e/10);  d<0: exp(-d/13) = 2^(-d*log2e/13)
// fmax(d*c1, d*c2) selects the correct branch for both signs.
#define C_POS ( 0.14426950408889634f)
#define C_NEG (-0.11097654160684334f)

__device__ __forceinline__ float ex2_approx(float x) {
    float r;
    asm("ex2.approx.f32 %0, %1;" : "=f"(r) : "f"(x));
    return r;
}

__device__ __forceinline__ void accum_elem(float p, float t, float& s_exp, float& s_sq) {
    float d = p - t;
    s_sq = fmaf(d, d, s_sq);
    float arg = fmaxf(d * C_POS, d * C_NEG);
    s_exp += ex2_approx(arg);      // the -1 is applied once at the end
}

__device__ __forceinline__ void accum4(float4 a, float4 b, float& s_exp, float& s_sq) {
    accum_elem(a.x, b.x, s_exp, s_sq);
    accum_elem(a.y, b.y, s_exp, s_sq);
    accum_elem(a.z, b.z, s_exp, s_sq);
    accum_elem(a.w, b.w, s_exp, s_sq);
}

__global__ void __launch_bounds__(REDUCE_THREADS) reduce_kernel(
    const float4* __restrict__ pred, const float4* __restrict__ tru, int n4)
{
    float s_exp = 0.0f;
    float s_sq = 0.0f;

    int idx = blockIdx.x * blockDim.x + threadIdx.x;
    int stride = gridDim.x * blockDim.x;

    // Unrolled x2: 4 independent 128-bit streaming loads front-batched
    int i = idx;
    for (; i + stride < n4; i += 2 * stride) {
        float4 a0 = __ldcs(&pred[i]);
        float4 b0 = __ldcs(&tru[i]);
        float4 a1 = __ldcs(&pred[i + stride]);
        float4 b1 = __ldcs(&tru[i + stride]);
        accum4(a0, b0, s_exp, s_sq);
        accum4(a1, b1, s_exp, s_sq);
    }
    if (i < n4) {
        float4 a = __ldcs(&pred[i]);
        float4 b = __ldcs(&tru[i]);
        accum4(a, b, s_exp, s_sq);
    }

    // Warp reduction (fp32 within warp)
    #pragma unroll
    for (int off = 16; off > 0; off >>= 1) {
        s_exp += __shfl_down_sync(0xFFFFFFFFu, s_exp, off);
        s_sq  += __shfl_down_sync(0xFFFFFFFFu, s_sq, off);
    }

    __shared__ double sh_exp[REDUCE_THREADS / 32];
    __shared__ double sh_sq[REDUCE_THREADS / 32];
    int wid = threadIdx.x >> 5;
    int lid = threadIdx.x & 31;
    if (lid == 0) {
        sh_exp[wid] = (double)s_exp;
        sh_sq[wid]  = (double)s_sq;
    }
    __syncthreads();

    if (threadIdx.x == 0) {
        double bs = 0.0, bq = 0.0;
        #pragma unroll
        for (int w = 0; w < REDUCE_THREADS / 32; w++) { bs += sh_exp[w]; bq += sh_sq[w]; }
        g_partials[blockIdx.x] = make_double2(bs, bq);
    }
}

__global__ void __launch_bounds__(FIN_THREADS) finalize_kernel(
    const float* __restrict__ theta_ptr, float* __restrict__ out,
    int n_total_div4, float inv_n)
{
    int tid = threadIdx.x;
    // 1184 partials, 1024 threads: thread t reads slot t, and t<160 reads t+1024
    double f_exp = 0.0, f_sq = 0.0;
    if (tid < REDUCE_BLOCKS) {
        double2 v = g_partials[tid];
        f_exp = v.x; f_sq = v.y;
    }
    int t2 = tid + FIN_THREADS;
    if (t2 < REDUCE_BLOCKS) {
        double2 v = g_partials[t2];
        f_exp += v.x; f_sq += v.y;
    }

    #pragma unroll
    for (int off = 16; off > 0; off >>= 1) {
        f_exp += __shfl_down_sync(0xFFFFFFFFu, f_exp, off);
        f_sq  += __shfl_down_sync(0xFFFFFFFFu, f_sq, off);
    }

    __shared__ double sh_exp[FIN_THREADS / 32];
    __shared__ double sh_sq[FIN_THREADS / 32];
    int wid = tid >> 5;
    int lid = tid & 31;
    if (lid == 0) { sh_exp[wid] = f_exp; sh_sq[wid] = f_sq; }
    __syncthreads();

    if (wid == 0) {
        double e = (lid < FIN_THREADS / 32) ? sh_exp[lid] : 0.0;
        double q = (lid < FIN_THREADS / 32) ? sh_sq[lid]  : 0.0;
        #pragma unroll
        for (int off = 16; off > 0; off >>= 1) {
            e += __shfl_down_sync(0xFFFFFFFFu, e, off);
            q += __shfl_down_sync(0xFFFFFFFFu, q, off);
        }
        if (lid == 0) {
            double n_total = (double)n_total_div4 * 4.0;
            double score = e - n_total;            // sum(exp(...) - 1)
            float theta = theta_ptr[0];
            double rmse = sqrt(q * (double)inv_n);
            out[0] = (float)((double)theta * score + (1.0 - (double)theta) * rmse);
        }
    }
}

extern "C" void kernel_launch(void* const* d_in, const int* in_sizes, int n_in,
                              void* d_out, int out_size) {
    const float* pred  = (const float*)d_in[0];
    const float* tru   = (const float*)d_in[1];
    const float* theta = (const float*)d_in[2];
    float* out = (float*)d_out;

    int n = in_sizes[0];           // 16777216
    int n4 = n >> 2;

    reduce_kernel<<<REDUCE_BLOCKS, REDUCE_THREADS>>>(
        (const float4*)pred, (const float4*)tru, n4);

    finalize_kernel<<<1, FIN_THREADS>>>(theta, out, n4, 1.0f / (float)n);
}